// round 15
// baseline (speedup 1.0000x reference)
#include <cuda_runtime.h>
#include <cfloat>

// DisturbanceRegressionLoss2Heads — t-split decomposition: 2 threads per
// float4-pixel-group (A: t=0..14, B: t=14..29), pair-combine via shfl_xor 16.
// Doubles resident warps while keeping LDG.128 load width.
// out: (8, 2, 30, 256, 256) fp32; target unused; output: scalar fp32 loss.

static constexpr int YT   = 30;
static constexpr int HWC  = 256 * 256;            // 65536
static constexpr int B    = 8;
static constexpr int NPIX = B * HWC;              // 524288
static constexpr int VEC  = 4;                    // pixels per float4 group
static constexpr int NG   = NPIX / VEC;           // 131072 groups
static constexpr int TPB  = 128;
static constexpr int NBLK = NG * 2 / TPB;         // 2048 (2 threads/group)

__device__ double       g_acc = 0.0;
__device__ unsigned int g_cnt = 0;

__global__ __launch_bounds__(TPB)
void disturbance_loss_kernel(const float* __restrict__ outp,
                             float* __restrict__ res) {
    const int tid  = threadIdx.x;
    const int lane = tid & 31;
    const int half = lane >> 4;                       // 0: t=0..14, 1: t=14..29
    const int gw   = (blockIdx.x * TPB + tid) >> 5;   // global warp id
    const int pg   = gw * 16 + (lane & 15);           // float4-group id
    const int b    = pg >> 14;                        // pg / (HWC/4)
    const int hw4  = pg & 16383;

    const float4* p0 = reinterpret_cast<const float4*>(
                           outp + (size_t)b * (2 * YT * HWC)) + hw4;  // out[:,0]
    const float4* p1 = p0 + (size_t)YT * (HWC / 4);                   // out[:,1]

    // ---- pass 1 (half range of t): argmin with prefix capture ----
    float prev[VEC], mn[VEC], py[VEC], pty[VEC], SyB[VEC], StyB[VEC];
    int   d[VEC];
#pragma unroll
    for (int l = 0; l < VEC; ++l) {
        mn[l] = (half == 0) ? -7.0f : FLT_MAX;        // A holds global default d=0
        d[l] = 0; py[l] = 0.f; pty[l] = 0.f; SyB[l] = 0.f; StyB[l] = 0.f;
        prev[l] = 0.f;
    }

    if (half == 0) {
#pragma unroll
        for (int t = 0; t <= 14; ++t) {
            float4 v4 = __ldg(p0 + (size_t)t * (HWC / 4));
            float v[VEC] = {v4.x, v4.y, v4.z, v4.w};
#pragma unroll
            for (int l = 0; l < VEC; ++l) {
                if (t >= 2) {                         // diff index 2..14
                    float dv = v[l] - prev[l];
                    if (dv < mn[l]) {
                        mn[l] = dv; d[l] = t;
                        SyB[l] = py[l]; StyB[l] = pty[l];
                    }
                }
                prev[l] = v[l];
                py[l]  += v[l];
                pty[l]  = fmaf((float)t, v[l], pty[l]);
            }
        }
    } else {
        {   // t = 14: prev only (sums belong to A)
            float4 v4 = __ldg(p0 + (size_t)14 * (HWC / 4));
            prev[0] = v4.x; prev[1] = v4.y; prev[2] = v4.z; prev[3] = v4.w;
        }
#pragma unroll
        for (int t = 15; t <= 29; ++t) {
            float4 v4 = __ldg(p0 + (size_t)t * (HWC / 4));
            float v[VEC] = {v4.x, v4.y, v4.z, v4.w};
#pragma unroll
            for (int l = 0; l < VEC; ++l) {
                if (t < YT - 1) {                     // diff index 15..28
                    float dv = v[l] - prev[l];
                    if (dv < mn[l]) {
                        mn[l] = dv; d[l] = t;
                        SyB[l] = py[l]; StyB[l] = pty[l];  // relative to t=15
                    }
                }
                prev[l] = v[l];
                py[l]  += v[l];
                pty[l]  = fmaf((float)t, v[l], pty[l]);
            }
        }
    }

    // ---- pair combine: exchange with partner (lane ^ 16) ----
    float scb[VEC], icb[VEC], sca[VEC], ica[VEC];
    int   dc[VEC];
#pragma unroll
    for (int l = 0; l < VEC; ++l) {
        float o_mn   = __shfl_xor_sync(0xffffffffu, mn[l],   16);
        int   o_d    = __shfl_xor_sync(0xffffffffu, d[l],    16);
        float o_py   = __shfl_xor_sync(0xffffffffu, py[l],   16);
        float o_pty  = __shfl_xor_sync(0xffffffffu, pty[l],  16);
        float o_SyB  = __shfl_xor_sync(0xffffffffu, SyB[l],  16);
        float o_StyB = __shfl_xor_sync(0xffffffffu, StyB[l], 16);

        // sort into A-values / B-values
        float mnA   = half ? o_mn   : mn[l];
        float mnB   = half ? mn[l]  : o_mn;
        int   dA    = half ? o_d    : d[l];
        int   dB    = half ? d[l]   : o_d;
        float pyA   = half ? o_py   : py[l];
        float pyB   = half ? py[l]  : o_py;
        float ptyA  = half ? o_pty  : pty[l];
        float ptyB  = half ? pty[l] : o_pty;
        float SyBA  = half ? o_SyB  : SyB[l];
        float SyBB  = half ? SyB[l] : o_SyB;
        float StyBA = half ? o_StyB : StyB[l];
        float StyBB = half ? StyB[l]: o_StyB;

        // first-occurrence min: ties go to A (all A-indices < B-indices)
        bool  useB = mnB < mnA;
        int   dd   = useB ? dB : dA;
        float Sy   = useB ? (pyA + SyBB)   : SyBA;    // B capture is rel. to t=15
        float Sty  = useB ? (ptyA + StyBB) : StyBA;
        float pyT  = pyA + pyB;
        float ptyT = ptyA + ptyB;

        dc[l] = dd;
        const float nb = (float)dd;
        const float na = (float)(YT - dd);            // >= 2

        // before-segment (may be empty: all sums 0 -> slope 0, icpt 0)
        float nsb  = fmaxf(nb, 1.f);
        float mxb  = 0.5f * nb * (nb - 1.f) / nsb;    // Sx / n_safe
        float myb  = Sy / nsb;
        float covb = Sty - mxb * Sy;
        float varb = nb * (nb * nb - 1.f) * (1.f / 12.f);
        float slb  = (varb > 0.f) ? covb / fmaxf(varb, 1.f) : 0.f;
        scb[l]     = fminf(fmaxf(slb, 0.f), 2.f);
        icb[l]     = fminf(fmaxf(myb - slb * mxb, 0.f), 100.f);

        // after-segment via total - prefix (x = t - d)
        float SyA  = pyT  - Sy;
        float SxyA = (ptyT - Sty) - nb * SyA;
        float mxa  = 0.5f * (na - 1.f);
        float mya  = SyA / na;
        float cova = SxyA - mxa * SyA;
        float vara = na * (na * na - 1.f) * (1.f / 12.f);
        float sla  = cova / fmaxf(vara, 1.f);         // na>=2 -> var>0
        sca[l]     = fminf(fmaxf(sla, 0.f), 2.f);
        ica[l]     = fminf(fmaxf(mya - sla * mxa, 0.f), 100.f);
    }

    // ---- pass 2 (own half of t) over out1: squared error ----
    float acc = 0.f;
    const int t0 = half ? 15 : 0;
    const int t1 = half ? 29 : 14;
#pragma unroll
    for (int t = 0; t < 15; ++t) {
        int tt = t0 + t;
        if (tt > t1) break;
        float4 y4 = __ldg(p1 + (size_t)tt * (HWC / 4));
        float y[VEC] = {y4.x, y4.y, y4.z, y4.w};
#pragma unroll
        for (int l = 0; l < VEC; ++l) {
            float f = (tt < dc[l]) ? fmaf(scb[l], (float)tt, icb[l])
                                   : fmaf(sca[l], (float)(tt - dc[l]), ica[l]);
            float r = f - y[l];
            acc = fmaf(r, r, acc);
        }
    }

    // ---- block reduction: warp shuffle -> shared -> one double atomic ----
#pragma unroll
    for (int o = 16; o > 0; o >>= 1) acc += __shfl_xor_sync(0xffffffffu, acc, o);
    __shared__ float sm[TPB / 32];
    const int wid = tid >> 5;
    if ((tid & 31) == 0) sm[wid] = acc;
    __syncthreads();
    if (wid == 0) {
        float s = (lane < TPB / 32) ? sm[lane] : 0.f;
#pragma unroll
        for (int o = (TPB / 32) >> 1; o > 0; o >>= 1)
            s += __shfl_xor_sync(0xffffffffu, s, o);
        if (lane == 0) {
            atomicAdd(&g_acc, (double)s);
            __threadfence();
            unsigned t = atomicInc(&g_cnt, NBLK - 1);   // wraps to 0 on last
            if (t == (unsigned)(NBLK - 1)) {
                double tot = atomicAdd(&g_acc, 0.0);    // coherent read
                *res = (float)(tot * (1.0 / ((double)YT * (double)NPIX)));
                atomicExch(reinterpret_cast<unsigned long long*>(&g_acc), 0ULL);
            }
        }
    }
}

extern "C" void kernel_launch(void* const* d_in, const int* in_sizes, int n_in,
                              void* d_out, int out_size) {
    (void)in_sizes; (void)n_in; (void)out_size;
    const float* outp = (const float*)d_in[0];      // 'out' per metadata order
    float*       res  = (float*)d_out;
    disturbance_loss_kernel<<<NBLK, TPB>>>(outp, res);
}

// round 16
// speedup vs baseline: 1.2729x; 1.2729x over previous
#include <cuda_runtime.h>

// DisturbanceRegressionLoss2Heads — two-pass prefix-capture, VEC=4 (R2 config),
// fast-divide coefficient math to shrink the inter-pass compute notch.
// out: (8, 2, 30, 256, 256) fp32; target unused; output: scalar fp32 loss.

static constexpr int YT   = 30;
static constexpr int HWC  = 256 * 256;            // 65536
static constexpr int B    = 8;
static constexpr int NPIX = B * HWC;              // 524288
static constexpr int VEC  = 4;                    // pixels per thread (float4)
static constexpr int TPB  = 256;
static constexpr int NBLK = NPIX / VEC / TPB;     // 512

__device__ double       g_acc = 0.0;
__device__ unsigned int g_cnt = 0;

__global__ __launch_bounds__(TPB)
void disturbance_loss_kernel(const float* __restrict__ outp,
                             float* __restrict__ res) {
    const int g   = blockIdx.x * TPB + threadIdx.x;   // float4-group id
    const int b   = g >> 14;                          // g / (HWC/4)
    const int hw4 = g & 16383;

    const float4* p0 = reinterpret_cast<const float4*>(
                           outp + (size_t)b * (2 * YT * HWC)) + hw4;  // out[:,0]
    const float4* p1 = p0 + (size_t)YT * (HWC / 4);                   // out[:,1]

    // ---- pass 1 over out0: argmin with prefix-sum capture ----
    float prev[VEC], mn[VEC], py[VEC], pty[VEC], SyB[VEC], StyB[VEC];
    int   d[VEC];
#pragma unroll
    for (int l = 0; l < VEC; ++l) {
        mn[l] = -7.0f; d[l] = 0;
        py[l] = 0.f; pty[l] = 0.f; SyB[l] = 0.f; StyB[l] = 0.f;
        prev[l] = 0.f;
    }

#pragma unroll
    for (int t = 0; t < YT; ++t) {
        float4 v4 = __ldg(p0 + (size_t)t * (HWC / 4));
        float v[VEC] = {v4.x, v4.y, v4.z, v4.w};
#pragma unroll
        for (int l = 0; l < VEC; ++l) {
            if (t >= 2 && t < YT - 1) {               // diff index 2..28
                float dv = v[l] - prev[l];
                if (dv < mn[l]) {                     // first-occurrence min
                    mn[l] = dv; d[l] = t;
                    SyB[l] = py[l]; StyB[l] = pty[l]; // prefix over t' < d
                }
            }
            prev[l] = v[l];
            py[l]  += v[l];
            pty[l]  = fmaf((float)t, v[l], pty[l]);
        }
    }

    // ---- per-pixel OLS coefficients (fast reciprocals; registers only) ----
    float scb[VEC], icb[VEC], sca[VEC], ica[VEC];
#pragma unroll
    for (int l = 0; l < VEC; ++l) {
        const float nb = (float)d[l];
        const float na = (float)(YT - d[l]);          // >= 2

        // before-segment (may be empty: all sums 0 -> slope 0, icpt 0)
        float rnsb = __fdividef(1.f, fmaxf(nb, 1.f));
        float mxb  = 0.5f * nb * (nb - 1.f) * rnsb;   // Sx / n_safe
        float myb  = SyB[l] * rnsb;
        float covb = StyB[l] - mxb * SyB[l];
        float varb = nb * (nb * nb - 1.f) * (1.f / 12.f);
        float slb  = (varb > 0.f) ? covb * __fdividef(1.f, fmaxf(varb, 1.f))
                                  : 0.f;
        scb[l]     = fminf(fmaxf(slb, 0.f), 2.f);
        icb[l]     = fminf(fmaxf(myb - slb * mxb, 0.f), 100.f);

        // after-segment via total - prefix (x = t - d)
        float SyA  = py[l]  - SyB[l];
        float SxyA = (pty[l] - StyB[l]) - nb * SyA;
        float mxa  = 0.5f * (na - 1.f);
        float mya  = SyA * __fdividef(1.f, na);
        float cova = SxyA - mxa * SyA;
        float vara = na * (na * na - 1.f) * (1.f / 12.f);
        float sla  = cova * __fdividef(1.f, fmaxf(vara, 1.f)); // na>=2 -> var>0
        sca[l]     = fminf(fmaxf(sla, 0.f), 2.f);
        ica[l]     = fminf(fmaxf(mya - sla * mxa, 0.f), 100.f);
    }

    // ---- pass 2 over out1: squared error of piecewise fit ----
    float acc = 0.f;
#pragma unroll
    for (int t = 0; t < YT; ++t) {
        float4 y4 = __ldg(p1 + (size_t)t * (HWC / 4));
        float y[VEC] = {y4.x, y4.y, y4.z, y4.w};
#pragma unroll
        for (int l = 0; l < VEC; ++l) {
            float f = (t < d[l]) ? fmaf(scb[l], (float)t, icb[l])
                                 : fmaf(sca[l], (float)(t - d[l]), ica[l]);
            float r = f - y[l];
            acc = fmaf(r, r, acc);
        }
    }

    // ---- block reduction: warp shuffle -> shared -> one double atomic ----
#pragma unroll
    for (int o = 16; o > 0; o >>= 1) acc += __shfl_xor_sync(0xffffffffu, acc, o);
    __shared__ float sm[TPB / 32];
    const int wid  = threadIdx.x >> 5;
    const int lane = threadIdx.x & 31;
    if (lane == 0) sm[wid] = acc;
    __syncthreads();
    if (wid == 0) {
        float s = (lane < TPB / 32) ? sm[lane] : 0.f;
#pragma unroll
        for (int o = (TPB / 32) >> 1; o > 0; o >>= 1)
            s += __shfl_xor_sync(0xffffffffu, s, o);
        if (lane == 0) {
            atomicAdd(&g_acc, (double)s);
            __threadfence();
            unsigned t = atomicInc(&g_cnt, NBLK - 1);   // wraps to 0 on last
            if (t == (unsigned)(NBLK - 1)) {
                double tot = atomicAdd(&g_acc, 0.0);    // coherent read
                *res = (float)(tot * (1.0 / ((double)YT * (double)NPIX)));
                atomicExch(reinterpret_cast<unsigned long long*>(&g_acc), 0ULL);
            }
        }
    }
}

extern "C" void kernel_launch(void* const* d_in, const int* in_sizes, int n_in,
                              void* d_out, int out_size) {
    (void)in_sizes; (void)n_in; (void)out_size;
    const float* outp = (const float*)d_in[0];      // 'out' per metadata order
    float*       res  = (float*)d_out;
    disturbance_loss_kernel<<<NBLK, TPB>>>(outp, res);
}

// round 17
// speedup vs baseline: 1.4848x; 1.1665x over previous
#include <cuda_runtime.h>

// DisturbanceRegressionLoss2Heads — two-pass prefix-capture, VEC=4 (R2 config),
// fast reciprocals + hard __launch_bounds__(256,4) to pin 64 regs / 4 CTAs/SM.
// out: (8, 2, 30, 256, 256) fp32; target unused; output: scalar fp32 loss.

static constexpr int YT   = 30;
static constexpr int HWC  = 256 * 256;            // 65536
static constexpr int B    = 8;
static constexpr int NPIX = B * HWC;              // 524288
static constexpr int VEC  = 4;                    // pixels per thread (float4)
static constexpr int TPB  = 256;
static constexpr int NBLK = NPIX / VEC / TPB;     // 512

__device__ double       g_acc = 0.0;
__device__ unsigned int g_cnt = 0;

__global__ __launch_bounds__(TPB, 4)              // pin 64 regs -> 4 CTAs/SM
void disturbance_loss_kernel(const float* __restrict__ outp,
                             float* __restrict__ res) {
    const int g   = blockIdx.x * TPB + threadIdx.x;   // float4-group id
    const int b   = g >> 14;                          // g / (HWC/4)
    const int hw4 = g & 16383;

    const float4* p0 = reinterpret_cast<const float4*>(
                           outp + (size_t)b * (2 * YT * HWC)) + hw4;  // out[:,0]
    const float4* p1 = p0 + (size_t)YT * (HWC / 4);                   // out[:,1]

    // ---- pass 1 over out0: argmin with prefix-sum capture ----
    float prev[VEC], mn[VEC], py[VEC], pty[VEC], SyB[VEC], StyB[VEC];
    int   d[VEC];
#pragma unroll
    for (int l = 0; l < VEC; ++l) {
        mn[l] = -7.0f; d[l] = 0;
        py[l] = 0.f; pty[l] = 0.f; SyB[l] = 0.f; StyB[l] = 0.f;
        prev[l] = 0.f;
    }

#pragma unroll
    for (int t = 0; t < YT; ++t) {
        float4 v4 = __ldg(p0 + (size_t)t * (HWC / 4));
        float v[VEC] = {v4.x, v4.y, v4.z, v4.w};
#pragma unroll
        for (int l = 0; l < VEC; ++l) {
            if (t >= 2 && t < YT - 1) {               // diff index 2..28
                float dv = v[l] - prev[l];
                if (dv < mn[l]) {                     // first-occurrence min
                    mn[l] = dv; d[l] = t;
                    SyB[l] = py[l]; StyB[l] = pty[l]; // prefix over t' < d
                }
            }
            prev[l] = v[l];
            py[l]  += v[l];
            pty[l]  = fmaf((float)t, v[l], pty[l]);
        }
    }

    // ---- per-pixel OLS coefficients (fast reciprocals; registers only) ----
    float scb[VEC], icb[VEC], sca[VEC], ica[VEC];
#pragma unroll
    for (int l = 0; l < VEC; ++l) {
        const float nb = (float)d[l];
        const float na = (float)(YT - d[l]);          // >= 2

        // before-segment (may be empty: all sums 0 -> slope 0, icpt 0)
        float rnsb = __fdividef(1.f, fmaxf(nb, 1.f));
        float mxb  = 0.5f * nb * (nb - 1.f) * rnsb;   // Sx / n_safe
        float myb  = SyB[l] * rnsb;
        float covb = StyB[l] - mxb * SyB[l];
        float varb = nb * (nb * nb - 1.f) * (1.f / 12.f);
        float slb  = (varb > 0.f) ? covb * __fdividef(1.f, fmaxf(varb, 1.f))
                                  : 0.f;
        scb[l]     = fminf(fmaxf(slb, 0.f), 2.f);
        icb[l]     = fminf(fmaxf(myb - slb * mxb, 0.f), 100.f);

        // after-segment via total - prefix (x = t - d)
        float SyA  = py[l]  - SyB[l];
        float SxyA = (pty[l] - StyB[l]) - nb * SyA;
        float mxa  = 0.5f * (na - 1.f);
        float mya  = SyA * __fdividef(1.f, na);
        float cova = SxyA - mxa * SyA;
        float vara = na * (na * na - 1.f) * (1.f / 12.f);
        float sla  = cova * __fdividef(1.f, fmaxf(vara, 1.f)); // na>=2 -> var>0
        sca[l]     = fminf(fmaxf(sla, 0.f), 2.f);
        ica[l]     = fminf(fmaxf(mya - sla * mxa, 0.f), 100.f);
    }

    // ---- pass 2 over out1: squared error of piecewise fit ----
    float acc = 0.f;
#pragma unroll
    for (int t = 0; t < YT; ++t) {
        float4 y4 = __ldg(p1 + (size_t)t * (HWC / 4));
        float y[VEC] = {y4.x, y4.y, y4.z, y4.w};
#pragma unroll
        for (int l = 0; l < VEC; ++l) {
            float f = (t < d[l]) ? fmaf(scb[l], (float)t, icb[l])
                                 : fmaf(sca[l], (float)(t - d[l]), ica[l]);
            float r = f - y[l];
            acc = fmaf(r, r, acc);
        }
    }

    // ---- block reduction: warp shuffle -> shared -> one double atomic ----
#pragma unroll
    for (int o = 16; o > 0; o >>= 1) acc += __shfl_xor_sync(0xffffffffu, acc, o);
    __shared__ float sm[TPB / 32];
    const int wid  = threadIdx.x >> 5;
    const int lane = threadIdx.x & 31;
    if (lane == 0) sm[wid] = acc;
    __syncthreads();
    if (wid == 0) {
        float s = (lane < TPB / 32) ? sm[lane] : 0.f;
#pragma unroll
        for (int o = (TPB / 32) >> 1; o > 0; o >>= 1)
            s += __shfl_xor_sync(0xffffffffu, s, o);
        if (lane == 0) {
            atomicAdd(&g_acc, (double)s);
            __threadfence();
            unsigned t = atomicInc(&g_cnt, NBLK - 1);   // wraps to 0 on last
            if (t == (unsigned)(NBLK - 1)) {
                double tot = atomicAdd(&g_acc, 0.0);    // coherent read
                *res = (float)(tot * (1.0 / ((double)YT * (double)NPIX)));
                atomicExch(reinterpret_cast<unsigned long long*>(&g_acc), 0ULL);
            }
        }
    }
}

extern "C" void kernel_launch(void* const* d_in, const int* in_sizes, int n_in,
                              void* d_out, int out_size) {
    (void)in_sizes; (void)n_in; (void)out_size;
    const float* outp = (const float*)d_in[0];      // 'out' per metadata order
    float*       res  = (float*)d_out;
    disturbance_loss_kernel<<<NBLK, TPB>>>(outp, res);
}